// round 14
// baseline (speedup 1.0000x reference)
#include <cuda_runtime.h>
#include <cuda_bf16.h>

// Problem constants (fixed shapes from reference)
#define NMAX   100000
#define NFEAT  512
#define NHID   8
#define NCLASS 16

// ---------------- scratch (device globals; no allocation allowed) ----------
__device__ float g_supp1[NMAX * NHID];    // x @ W1
__device__ float g_xr   [NMAX * NHID];    // gamma*relu(0.5*(xv^2 - x2v2))+beta
__device__ float g_agg1 [NMAX * NHID];    // spmm1 accumulator
__device__ float g_supp2[NMAX * NCLASS];  // h @ W2
__device__ float g_agg2 [NMAX * NCLASS];  // spmm2 accumulator

// ---------------- f32x2 packed-math helpers (Blackwell) --------------------
__device__ __forceinline__ unsigned long long pk2(float a, float b) {
    unsigned long long r;
    asm("mov.b64 %0, {%1, %2};" : "=l"(r) : "f"(a), "f"(b));
    return r;
}
__device__ __forceinline__ unsigned long long ffma2(unsigned long long a,
                                                    unsigned long long b,
                                                    unsigned long long c) {
    unsigned long long d;
    asm("fma.rn.f32x2 %0, %1, %2, %3;" : "=l"(d) : "l"(a), "l"(b), "l"(c));
    return d;
}
__device__ __forceinline__ void upk2(unsigned long long v, float& a, float& b) {
    asm("mov.b64 {%0, %1}, %2;" : "=f"(a), "=f"(b) : "l"(v));
}
// vector reduction to global (sm_90+), no return value
__device__ __forceinline__ void red4(float* p, float a, float b, float c, float d) {
    asm volatile("red.global.add.v4.f32 [%0], {%1, %2, %3, %4};"
                 :: "l"(p), "f"(a), "f"(b), "f"(c), "f"(d) : "memory");
}

// ---------------- kernel 0: zero the aggregation buffers -------------------
__global__ void k_zero(int n) {
    int i = blockIdx.x * blockDim.x + threadIdx.x;
    float4 z = make_float4(0.f, 0.f, 0.f, 0.f);
    int n2 = n * 2;            // agg1: n*8 floats = 2n float4
    int n6 = n * 6;            // agg2: n*16 floats = 4n float4
    if (i < n2)       reinterpret_cast<float4*>(g_agg1)[i] = z;
    else if (i < n6)  reinterpret_cast<float4*>(g_agg2)[i - n2] = z;
}

// ---------------- kernel 1: fused node transform ----------------------------
// support1 = x@W1 ; xr = gamma*relu(0.5*((x@V)^2 - (x^2)@(V^2))) + beta
// One warp = 32 nodes (one node per lane), x staged in shared (KT=32 tiles),
// W broadcast from shared as packed f32x2 pairs, 12 FFMA2 per k per warp.
#define KT 32
#define K1_WARPS 8
#define K1_SX_STRIDE 33
#define K1_SMEM_FLOATS (3 * NFEAT * NHID + K1_WARPS * 32 * K1_SX_STRIDE + 16)

__global__ void __launch_bounds__(256)
k1_transform(const float* __restrict__ x,
             const float* __restrict__ W1,
             const float* __restrict__ V,
             const float* __restrict__ gamma,
             const float* __restrict__ beta,
             int n)
{
    extern __shared__ __align__(16) float sm[];
    float* sW1 = sm;                       // 4096 floats
    float* sV  = sm + NFEAT * NHID;        // 4096
    float* sV2 = sm + 2 * NFEAT * NHID;    // 4096
    float* sx  = sm + 3 * NFEAT * NHID;    // 8*32*33
    float* sgb = sx + K1_WARPS * 32 * K1_SX_STRIDE; // 16

    int tid = threadIdx.x;
    for (int i = tid; i < NFEAT * NHID; i += blockDim.x) {
        float w = W1[i];  sW1[i] = w;
        float v = V[i];   sV[i]  = v;  sV2[i] = v * v;
    }
    if (tid < NHID) { sgb[tid] = gamma[tid]; sgb[NHID + tid] = beta[tid]; }
    __syncthreads();

    const int warp = tid >> 5, lane = tid & 31;
    float* sxw = sx + warp * (32 * K1_SX_STRIDE);
    const int nodeBase = blockIdx.x * 256 + warp * 32;
    const int myNode = nodeBase + lane;

    const ulonglong2* pW1 = reinterpret_cast<const ulonglong2*>(sW1);
    const ulonglong2* pV  = reinterpret_cast<const ulonglong2*>(sV);
    const ulonglong2* pQ  = reinterpret_cast<const ulonglong2*>(sV2);

    unsigned long long aW[4] = {0ull, 0ull, 0ull, 0ull};
    unsigned long long aX[4] = {0ull, 0ull, 0ull, 0ull};
    unsigned long long aQ[4] = {0ull, 0ull, 0ull, 0ull};

    const int r0 = lane >> 3;          // 0..3
    const int c0 = (lane & 7) * 4;     // 0,4,...,28

#pragma unroll 1
    for (int kt = 0; kt < NFEAT; kt += KT) {
        // stage x tile: 32 nodes x 32 k, coalesced float4 loads, scalar STS
#pragma unroll
        for (int i = 0; i < 8; i++) {
            int row = r0 + i * 4;
            int node = nodeBase + row;
            if (node >= n) node = n - 1;
            float4 v4 = *reinterpret_cast<const float4*>(x + (size_t)node * NFEAT + kt + c0);
            float* d = sxw + row * K1_SX_STRIDE + c0;
            d[0] = v4.x; d[1] = v4.y; d[2] = v4.z; d[3] = v4.w;
        }
        __syncwarp();
        const float* myx = sxw + lane * K1_SX_STRIDE;
#pragma unroll
        for (int kk = 0; kk < KT; kk++) {
            float xv = myx[kk];
            float x2 = xv * xv;
            unsigned long long xp  = pk2(xv, xv);
            unsigned long long x2p = pk2(x2, x2);
            int k2 = (kt + kk) * 2;
            ulonglong2 wa = pW1[k2], wb = pW1[k2 + 1];
            aW[0] = ffma2(xp, wa.x, aW[0]);  aW[1] = ffma2(xp, wa.y, aW[1]);
            aW[2] = ffma2(xp, wb.x, aW[2]);  aW[3] = ffma2(xp, wb.y, aW[3]);
            ulonglong2 va = pV[k2],  vb = pV[k2 + 1];
            aX[0] = ffma2(xp, va.x, aX[0]);  aX[1] = ffma2(xp, va.y, aX[1]);
            aX[2] = ffma2(xp, vb.x, aX[2]);  aX[3] = ffma2(xp, vb.y, aX[3]);
            ulonglong2 qa = pQ[k2],  qb = pQ[k2 + 1];
            aQ[0] = ffma2(x2p, qa.x, aQ[0]); aQ[1] = ffma2(x2p, qa.y, aQ[1]);
            aQ[2] = ffma2(x2p, qb.x, aQ[2]); aQ[3] = ffma2(x2p, qb.y, aQ[3]);
        }
        __syncwarp();
    }

    if (myNode < n) {
        float o[8], xvv[8], qq[8];
        upk2(aW[0], o[0], o[1]);   upk2(aW[1], o[2], o[3]);
        upk2(aW[2], o[4], o[5]);   upk2(aW[3], o[6], o[7]);
        upk2(aX[0], xvv[0], xvv[1]); upk2(aX[1], xvv[2], xvv[3]);
        upk2(aX[2], xvv[4], xvv[5]); upk2(aX[3], xvv[6], xvv[7]);
        upk2(aQ[0], qq[0], qq[1]);   upk2(aQ[1], qq[2], qq[3]);
        upk2(aQ[2], qq[4], qq[5]);   upk2(aQ[3], qq[6], qq[7]);

        float4* ds = reinterpret_cast<float4*>(g_supp1 + (size_t)myNode * NHID);
        ds[0] = make_float4(o[0], o[1], o[2], o[3]);
        ds[1] = make_float4(o[4], o[5], o[6], o[7]);

        float xr[8];
#pragma unroll
        for (int j = 0; j < NHID; j++) {
            float t = 0.5f * (xvv[j] * xvv[j] - qq[j]);
            t = fmaxf(t, 0.f);
            xr[j] = sgb[j] * t + sgb[NHID + j];
        }
        float4* dr = reinterpret_cast<float4*>(g_xr + (size_t)myNode * NHID);
        dr[0] = make_float4(xr[0], xr[1], xr[2], xr[3]);
        dr[1] = make_float4(xr[4], xr[5], xr[6], xr[7]);
    }
}

// ---------------- kernel 2: spmm1 (agg1 += val * supp1[col]) ---------------
__global__ void k_spmm1(const int* __restrict__ rows,
                        const int* __restrict__ cols,
                        const float* __restrict__ vals, int e)
{
    int i = blockIdx.x * blockDim.x + threadIdx.x;
    if (i >= e) return;
    int r = rows[i], c = cols[i];
    float v = vals[i];
    const float4* s = reinterpret_cast<const float4*>(g_supp1 + (size_t)c * NHID);
    float4 a = s[0], b = s[1];
    float* dst = g_agg1 + (size_t)r * NHID;
    red4(dst,     a.x * v, a.y * v, a.z * v, a.w * v);
    red4(dst + 4, b.x * v, b.y * v, b.z * v, b.w * v);
}

// ---------------- kernel 3: mid transform (bias/relu/h/W2) -----------------
__global__ void k_mid(const float* __restrict__ b1,
                      const float* __restrict__ W2, int n)
{
    __shared__ float sW2[NHID * NCLASS];
    __shared__ float sb1[NHID];
    if (threadIdx.x < NHID * NCLASS) sW2[threadIdx.x] = W2[threadIdx.x];
    if (threadIdx.x < NHID)          sb1[threadIdx.x] = b1[threadIdx.x];
    __syncthreads();
    int i = blockIdx.x * blockDim.x + threadIdx.x;
    if (i >= n) return;

    float ag[8], xr[8];
    const float4* a = reinterpret_cast<const float4*>(g_agg1 + (size_t)i * NHID);
    const float4* r = reinterpret_cast<const float4*>(g_xr  + (size_t)i * NHID);
    float4 a0 = a[0], a1 = a[1], r0 = r[0], r1 = r[1];
    ag[0]=a0.x; ag[1]=a0.y; ag[2]=a0.z; ag[3]=a0.w; ag[4]=a1.x; ag[5]=a1.y; ag[6]=a1.z; ag[7]=a1.w;
    xr[0]=r0.x; xr[1]=r0.y; xr[2]=r0.z; xr[3]=r0.w; xr[4]=r1.x; xr[5]=r1.y; xr[6]=r1.z; xr[7]=r1.w;

    float h[8];
#pragma unroll
    for (int k = 0; k < NHID; k++) {
        float t = fmaxf(ag[k] + sb1[k], 0.f);
        h[k] = 0.5f * (t + xr[k]);
    }
    float acc[NCLASS];
#pragma unroll
    for (int j = 0; j < NCLASS; j++) acc[j] = 0.f;
#pragma unroll
    for (int k = 0; k < NHID; k++) {
        float hk = h[k];
#pragma unroll
        for (int j = 0; j < NCLASS; j++) acc[j] = fmaf(hk, sW2[k * NCLASS + j], acc[j]);
    }
    float4* o = reinterpret_cast<float4*>(g_supp2 + (size_t)i * NCLASS);
    o[0] = make_float4(acc[0],  acc[1],  acc[2],  acc[3]);
    o[1] = make_float4(acc[4],  acc[5],  acc[6],  acc[7]);
    o[2] = make_float4(acc[8],  acc[9],  acc[10], acc[11]);
    o[3] = make_float4(acc[12], acc[13], acc[14], acc[15]);
}

// ---------------- kernel 4: spmm2 (agg2 += val * supp2[col]) ---------------
__global__ void k_spmm2(const int* __restrict__ rows,
                        const int* __restrict__ cols,
                        const float* __restrict__ vals, int e)
{
    int i = blockIdx.x * blockDim.x + threadIdx.x;
    if (i >= e) return;
    int r = rows[i], c = cols[i];
    float v = vals[i];
    const float4* s = reinterpret_cast<const float4*>(g_supp2 + (size_t)c * NCLASS);
    float* dst = g_agg2 + (size_t)r * NCLASS;
#pragma unroll
    for (int q = 0; q < 4; q++) {
        float4 a = s[q];
        red4(dst + q * 4, a.x * v, a.y * v, a.z * v, a.w * v);
    }
}

// ---------------- kernel 5: + b2, log_softmax -------------------------------
__global__ void k_final(const float* __restrict__ b2,
                        float* __restrict__ out, int n)
{
    __shared__ float sb2[NCLASS];
    if (threadIdx.x < NCLASS) sb2[threadIdx.x] = b2[threadIdx.x];
    __syncthreads();
    int i = blockIdx.x * blockDim.x + threadIdx.x;
    if (i >= n) return;

    float v[NCLASS];
    const float4* a = reinterpret_cast<const float4*>(g_agg2 + (size_t)i * NCLASS);
#pragma unroll
    for (int q = 0; q < 4; q++) {
        float4 t = a[q];
        v[q*4+0] = t.x + sb2[q*4+0];
        v[q*4+1] = t.y + sb2[q*4+1];
        v[q*4+2] = t.z + sb2[q*4+2];
        v[q*4+3] = t.w + sb2[q*4+3];
    }
    float m = v[0];
#pragma unroll
    for (int j = 1; j < NCLASS; j++) m = fmaxf(m, v[j]);
    float s = 0.f;
#pragma unroll
    for (int j = 0; j < NCLASS; j++) s += expf(v[j] - m);
    float l = m + logf(s);
    float4* o = reinterpret_cast<float4*>(out + (size_t)i * NCLASS);
#pragma unroll
    for (int q = 0; q < 4; q++)
        o[q] = make_float4(v[q*4+0] - l, v[q*4+1] - l, v[q*4+2] - l, v[q*4+3] - l);
}

// ---------------- launch ----------------------------------------------------
extern "C" void kernel_launch(void* const* d_in, const int* in_sizes, int n_in,
                              void* d_out, int out_size)
{
    const float* x        = (const float*)d_in[0];
    const int*   adj_rows = (const int*)  d_in[1];
    const int*   adj_cols = (const int*)  d_in[2];
    const float* adj_vals = (const float*)d_in[3];
    const float* W1       = (const float*)d_in[4];
    const float* b1       = (const float*)d_in[5];
    const float* W2       = (const float*)d_in[6];
    const float* b2       = (const float*)d_in[7];
    const float* V        = (const float*)d_in[8];
    const float* gamma    = (const float*)d_in[9];
    const float* beta     = (const float*)d_in[10];
    float* out = (float*)d_out;

    const int n = in_sizes[0] / NFEAT;
    const int e = in_sizes[1];

    const int smem1 = K1_SMEM_FLOATS * (int)sizeof(float);
    cudaFuncSetAttribute(k1_transform, cudaFuncAttributeMaxDynamicSharedMemorySize, smem1);

    // zero aggregation buffers (6n float4)
    k_zero<<<(6 * n + 255) / 256, 256>>>(n);
    // fused node transform (256 nodes per block)
    k1_transform<<<(n + 255) / 256, 256, smem1>>>(x, W1, V, gamma, beta, n);
    // spmm1
    k_spmm1<<<(e + 255) / 256, 256>>>(adj_rows, adj_cols, adj_vals, e);
    // bias + relu + combine + h@W2
    k_mid<<<(n + 255) / 256, 256>>>(b1, W2, n);
    // spmm2
    k_spmm2<<<(e + 255) / 256, 256>>>(adj_rows, adj_cols, adj_vals, e);
    // + b2, log_softmax
    k_final<<<(n + 255) / 256, 256>>>(b2, out, n);
}